// round 1
// baseline (speedup 1.0000x reference)
#include <cuda_runtime.h>
#include <math.h>

// Problem constants (fixed shapes for this problem)
#define NN 50000
#define EE 400000
#define GG 256
#define HH 256
#define NDEPTH 6

// ---------------- scratch (device globals; no allocations allowed) ----------
__device__ float d_h[NN * HH];   // node state
__device__ float d_t[NN * HH];   // intermediate t
__device__ float d_g[NN * HH];   // GEMM output (pre-aggregation)
__device__ int   d_deg_in[NN];
__device__ int   d_deg_out[NN];
__device__ int   d_cursor[NN];
__device__ int   d_rowptr[NN + 1];
__device__ int   d_eid[EE];      // edge ids sorted by dst
__device__ float d_norm_o[NN];
__device__ float d_norm_i[NN];
__device__ float d_pooled[GG * HH];
__device__ int   d_cnt[GG];

// ---------------- helpers ----------------------------------------------------
__device__ __forceinline__ float block_sum_256(float v, float* red) {
  #pragma unroll
  for (int o = 16; o > 0; o >>= 1) v += __shfl_down_sync(0xffffffffu, v, o);
  int lane = threadIdx.x & 31, w = threadIdx.x >> 5;
  if (lane == 0) red[w] = v;
  __syncthreads();
  if (threadIdx.x < 8) {
    float x = red[threadIdx.x];
    #pragma unroll
    for (int o = 4; o > 0; o >>= 1) x += __shfl_down_sync(0xffu, x, o);
    if (threadIdx.x == 0) red[0] = x;
  }
  __syncthreads();
  float r = red[0];
  __syncthreads();
  return r;
}

// ---------------- preprocessing ----------------------------------------------
__global__ void k_zero() {
  int i = blockIdx.x * blockDim.x + threadIdx.x;
  if (i < NN) { d_deg_in[i] = 0; d_deg_out[i] = 0; d_cursor[i] = 0; }
  if (i < GG * HH) d_pooled[i] = 0.f;
  if (i < GG) d_cnt[i] = 0;
}

__global__ void k_hist(const int* __restrict__ src, const int* __restrict__ dst) {
  int e = blockIdx.x * blockDim.x + threadIdx.x;
  if (e < EE) {
    atomicAdd(&d_deg_in[dst[e]], 1);
    atomicAdd(&d_deg_out[src[e]], 1);
  }
}

// exclusive scan of d_deg_in -> d_rowptr (single block, 1024 threads)
__global__ void k_scan() {
  __shared__ int warp_tot[32];
  __shared__ int s_carry;
  int t = threadIdx.x, lane = t & 31, w = t >> 5;
  if (t == 0) s_carry = 0;
  __syncthreads();
  for (int base = 0; base < NN; base += 1024) {
    int v = (base + t < NN) ? d_deg_in[base + t] : 0;
    int x = v;
    #pragma unroll
    for (int o = 1; o < 32; o <<= 1) {
      int y = __shfl_up_sync(0xffffffffu, x, o);
      if (lane >= o) x += y;
    }
    if (lane == 31) warp_tot[w] = x;
    __syncthreads();
    if (w == 0) {
      int y = warp_tot[lane];
      int z = y;
      #pragma unroll
      for (int o = 1; o < 32; o <<= 1) {
        int q = __shfl_up_sync(0xffffffffu, z, o);
        if (lane >= o) z += q;
      }
      warp_tot[lane] = z - y;  // exclusive warp offsets
    }
    __syncthreads();
    int incl = x + warp_tot[w];      // block-inclusive
    int carry = s_carry;
    if (base + t < NN) d_rowptr[base + t] = carry + incl - v;  // exclusive
    __syncthreads();
    if (t == 1023) s_carry = carry + incl;
    __syncthreads();
  }
  if (threadIdx.x == 0) d_rowptr[NN] = s_carry;
}

__global__ void k_fill(const int* __restrict__ dst) {
  int e = blockIdx.x * blockDim.x + threadIdx.x;
  if (e < EE) {
    int dnode = dst[e];
    int pos = atomicAdd(&d_cursor[dnode], 1);
    d_eid[d_rowptr[dnode] + pos] = e;
  }
}

__global__ void k_norms() {
  int i = blockIdx.x * blockDim.x + threadIdx.x;
  if (i < NN) {
    int di = d_deg_in[i];
    int dq = d_deg_out[i];
    d_norm_i[i] = (di > 0) ? rsqrtf((float)di) : 0.f;
    d_norm_o[i] = (dq > 0) ? rsqrtf((float)dq) : 0.f;
  }
}

// ---------------- input projection: g = (concat(a,c,x) * norm_o) @ W_in -----
__global__ void __launch_bounds__(256) k_inproj(
    const float* __restrict__ a_t, const float* __restrict__ c_t,
    const float* __restrict__ x_t, const float* __restrict__ W_in) {
  __shared__ float f[16][27];
  int j = threadIdx.x;
  int row0 = blockIdx.x * 16;
  float w[27];
  #pragma unroll
  for (int k = 0; k < 27; k++) w[k] = W_in[k * HH + j];
  int r = j >> 4, c = j & 15;
  int node = row0 + r;
  bool ok = node < NN;
  f[r][c] = ok ? a_t[node * 16 + c] : 0.f;
  if (c < 8) f[r][16 + c] = ok ? c_t[node * 8 + c] : 0.f;
  if (c < 3) f[r][24 + c] = ok ? x_t[node * 3 + c] : 0.f;
  __syncthreads();
  for (int rr = 0; rr < 16; rr++) {
    int nn = row0 + rr;
    if (nn >= NN) break;
    float acc = 0.f;
    #pragma unroll
    for (int k = 0; k < 27; k++) acc += w[k] * f[rr][k];
    d_g[(size_t)nn * HH + j] = acc * d_norm_o[nn];
  }
}

// ---------------- SGEMM: C(d_g) = A @ B, rows scaled by norm_o --------------
// A: [M,256] (d_h or d_t), B: [256,256], 128x128 tile, 8x8 microtile, 256 thr
__global__ void __launch_bounds__(256) k_gemm(int a_sel, const float* __restrict__ B, int M) {
  __shared__ float As[16][128];
  __shared__ float Bs[16][128];
  const float* A = a_sel ? d_t : d_h;
  const int tid = threadIdx.x;
  const int tx = tid & 15;
  const int ty = tid >> 4;
  const int bm = blockIdx.x * 128;
  const int bn = blockIdx.y * 128;

  const int arow = tid >> 2;         // 0..63
  const int ak   = (tid & 3) << 2;   // 0,4,8,12
  const int bk   = tid >> 5;         // 0..7
  const int bcol = (tid & 31) << 2;  // 0..124

  float acc[8][8];
  #pragma unroll
  for (int i = 0; i < 8; i++)
    #pragma unroll
    for (int j = 0; j < 8; j++) acc[i][j] = 0.f;

  for (int k0 = 0; k0 < 256; k0 += 16) {
    #pragma unroll
    for (int h = 0; h < 2; h++) {
      int r = arow + h * 64;
      int grow = bm + r;
      float4 av = make_float4(0.f, 0.f, 0.f, 0.f);
      if (grow < M) av = *(const float4*)(A + (size_t)grow * 256 + k0 + ak);
      As[ak + 0][r] = av.x; As[ak + 1][r] = av.y;
      As[ak + 2][r] = av.z; As[ak + 3][r] = av.w;
    }
    #pragma unroll
    for (int h = 0; h < 2; h++) {
      int r = bk + h * 8;
      float4 bv = *(const float4*)(B + (size_t)(k0 + r) * 256 + bn + bcol);
      *(float4*)&Bs[r][bcol] = bv;
    }
    __syncthreads();
    #pragma unroll
    for (int k = 0; k < 16; k++) {
      float a[8], b[8];
      *(float4*)&a[0] = *(float4*)&As[k][ty * 8];
      *(float4*)&a[4] = *(float4*)&As[k][ty * 8 + 4];
      *(float4*)&b[0] = *(float4*)&Bs[k][tx * 8];
      *(float4*)&b[4] = *(float4*)&Bs[k][tx * 8 + 4];
      #pragma unroll
      for (int i = 0; i < 8; i++)
        #pragma unroll
        for (int j = 0; j < 8; j++) acc[i][j] += a[i] * b[j];
    }
    __syncthreads();
  }
  #pragma unroll
  for (int i = 0; i < 8; i++) {
    int row = bm + ty * 8 + i;
    if (row >= M) break;
    float s = d_norm_o[row];
    float4 v0, v1;
    v0.x = acc[i][0] * s; v0.y = acc[i][1] * s; v0.z = acc[i][2] * s; v0.w = acc[i][3] * s;
    v1.x = acc[i][4] * s; v1.y = acc[i][5] * s; v1.z = acc[i][6] * s; v1.w = acc[i][7] * s;
    *(float4*)(d_g + (size_t)row * 256 + bn + tx * 8)     = v0;
    *(float4*)(d_g + (size_t)row * 256 + bn + tx * 8 + 4) = v1;
  }
}

// ---------------- first aggregation (with fused edge-linear mean) -----------
__global__ void __launch_bounds__(256) k_agg0(
    const float* __restrict__ e_t, const int* __restrict__ src,
    const float* __restrict__ W_e, const float* __restrict__ b_in,
    const float* __restrict__ b_e) {
  __shared__ int s_eid[64];
  __shared__ int s_src[64];
  __shared__ float s_et[64][16];
  int n = blockIdx.x, j = threadIdx.x;
  float we[16];
  #pragma unroll
  for (int k = 0; k < 16; k++) we[k] = W_e[k * HH + j];
  int beg = d_rowptr[n], end = d_rowptr[n + 1];
  float acc = 0.f, eacc = 0.f;
  for (int base = beg; base < end; base += 64) {
    int cnt = min(64, end - base);
    __syncthreads();
    if (j < cnt) {
      int eid = d_eid[base + j];
      s_eid[j] = eid;
      s_src[j] = src[eid];
    }
    __syncthreads();
    for (int q = j; q < cnt * 16; q += 256) {
      int r = q >> 4, c = q & 15;
      s_et[r][c] = e_t[(size_t)s_eid[r] * 16 + c];
    }
    __syncthreads();
    for (int t = 0; t < cnt; t++) {
      acc += d_g[(size_t)s_src[t] * HH + j];
      float ea = 0.f;
      #pragma unroll
      for (int k = 0; k < 16; k++) ea += we[k] * s_et[t][k];
      eacc += ea;
    }
  }
  int deg = end - beg;
  float v = acc * d_norm_i[n] + b_in[j];
  if (deg > 0) v += eacc / (float)deg + b_e[j];
  d_h[(size_t)n * HH + j] = v;
}

// ---------------- layer aggregation: *norm_i+b, LN, SiLU, (+residual) -------
// resid_mode=0: out=d_t (no residual); resid_mode=1: out=d_h, add d_h residual
__global__ void __launch_bounds__(256) k_agg(
    const int* __restrict__ src, const float* __restrict__ bias,
    const float* __restrict__ gamma, const float* __restrict__ beta,
    int resid_mode) {
  __shared__ int s_src[256];
  __shared__ float red[8];
  int n = blockIdx.x, j = threadIdx.x;
  int beg = d_rowptr[n], end = d_rowptr[n + 1];
  float acc = 0.f;
  for (int base = beg; base < end; base += 256) {
    int cnt = min(256, end - base);
    __syncthreads();
    if (j < cnt) s_src[j] = src[d_eid[base + j]];
    __syncthreads();
    for (int t = 0; t < cnt; t++) acc += d_g[(size_t)s_src[t] * HH + j];
  }
  float v = acc * d_norm_i[n] + bias[j];
  float mu = block_sum_256(v, red) * (1.f / HH);
  float dd = v - mu;
  float var = block_sum_256(dd * dd, red) * (1.f / HH);
  float y = dd * rsqrtf(var + 1e-5f) * gamma[j] + beta[j];
  y = y / (1.f + __expf(-y));   // SiLU
  size_t idx = (size_t)n * HH + j;
  if (resid_mode) {
    d_h[idx] = y + d_h[idx];
  } else {
    d_t[idx] = y;
  }
}

// ---------------- pooling + head ---------------------------------------------
__global__ void k_pool(const int* __restrict__ gid) {
  int n = blockIdx.x, j = threadIdx.x;
  int g = gid[n];
  atomicAdd(&d_pooled[g * HH + j], d_h[(size_t)n * HH + j]);
  if (j == 0) atomicAdd(&d_cnt[g], 1);
}

__global__ void k_head(const float* __restrict__ W_head,
                       const float* __restrict__ b_head,
                       float* __restrict__ out) {
  __shared__ float red[8];
  int g = blockIdx.x, j = threadIdx.x;
  float c = (float)d_cnt[g];
  float v = d_pooled[g * HH + j] / fmaxf(c, 1.f) * W_head[j];
  float s = block_sum_256(v, red);
  if (j == 0) {
    float x = s + b_head[0];
    out[g] = (x > 20.f) ? x : log1pf(expf(x));
  }
}

// ---------------- launcher ----------------------------------------------------
extern "C" void kernel_launch(void* const* d_in, const int* in_sizes, int n_in,
                              void* d_out, int out_size) {
  const float* a_t   = (const float*)d_in[0];
  const float* c_t   = (const float*)d_in[1];
  const float* x_t   = (const float*)d_in[2];
  const float* e_t   = (const float*)d_in[3];
  const int*   src   = (const int*)d_in[4];
  const int*   dst   = (const int*)d_in[5];
  const int*   gid   = (const int*)d_in[6];
  const float* W_in  = (const float*)d_in[7];
  const float* b_in  = (const float*)d_in[8];
  const float* W_e   = (const float*)d_in[9];
  const float* b_e   = (const float*)d_in[10];
  const float* Wc1   = (const float*)d_in[11];
  const float* bc1   = (const float*)d_in[12];
  const float* g1    = (const float*)d_in[13];
  const float* be1   = (const float*)d_in[14];
  const float* Wc2   = (const float*)d_in[15];
  const float* bc2   = (const float*)d_in[16];
  const float* g2    = (const float*)d_in[17];
  const float* be2   = (const float*)d_in[18];
  const float* W_hd  = (const float*)d_in[19];
  const float* b_hd  = (const float*)d_in[20];
  float* out = (float*)d_out;

  // preprocessing: degrees, CSR by dst, norms
  k_zero<<<(GG * HH + 255) / 256, 256>>>();
  k_hist<<<(EE + 255) / 256, 256>>>(src, dst);
  k_scan<<<1, 1024>>>();
  k_fill<<<(EE + 255) / 256, 256>>>(dst);
  k_norms<<<(NN + 255) / 256, 256>>>();

  // input projection + first aggregation (fused edge-feature mean)
  k_inproj<<<(NN + 15) / 16, 256>>>(a_t, c_t, x_t, W_in);
  k_agg0<<<NN, 256>>>(e_t, src, W_e, b_in, b_e);

  dim3 ggrid((NN + 127) / 128, 2);
  for (int l = 0; l < NDEPTH; l++) {
    k_gemm<<<ggrid, 256>>>(0, Wc1 + (size_t)l * HH * HH, NN);           // d_h -> d_g
    k_agg<<<NN, 256>>>(src, bc1 + l * HH, g1 + l * HH, be1 + l * HH, 0); // d_g -> d_t
    k_gemm<<<ggrid, 256>>>(1, Wc2 + (size_t)l * HH * HH, NN);           // d_t -> d_g
    k_agg<<<NN, 256>>>(src, bc2 + l * HH, g2 + l * HH, be2 + l * HH, 1); // d_g -> d_h (+resid)
  }

  // mean pool per graph + head + softplus
  k_pool<<<NN, 256>>>(gid);
  k_head<<<GG, 256>>>(W_hd, b_hd, out);
}